// round 14
// baseline (speedup 1.0000x reference)
#include <cuda_runtime.h>

// ============================================================================
// AdapterSubnet top-k binary mask via sampled-bracket exact radix selection.
//
// key(x) = float_as_uint(|x|)  (31-bit, monotone with |x|)
// coarse bin = key >> 18  (8192 bins); band = 3 coarse bins around sampled
// threshold bin; rel = key - lo_key  (< 3*2^18).
// Selection inside the band: level-1 histogram h1[rel>>7] (6144 bins,
// L2-resident, filled by asn_mark), level-2 histogram h3[rel&127] over the
// winning level-1 bin (filled by asn_sel2 from the compacted candidates).
// Tie rule (stable argsort ascending, keep tail): among elements with
// key == threshold, keep the ones with LARGEST original indices.
// ============================================================================

#define SHIFT 18
#define NB_COARSE (1 << (31 - SHIFT))   // 8192
#define RANGE_COARSE 3
#define RB (RANGE_COARSE << SHIFT)      // 786,432 rel values
#define H1BINS (RB >> 7)                // 6144
#define CAND_CAP (1u << 20)             // 1,048,576 candidates per matrix
#define EQ_CAP 65536
#define NWARP 16                        // 512 threads in asn_mark
#define WBUF 96                         // per-warp staging entries
#define WFLUSH 64                       // flush threshold
#define SAMP_PM 32768                   // samples per matrix (1024 x 128B lines)

__device__ unsigned g_shist[2][NB_COARSE];
__device__ unsigned g_h1[2][H1BINS];
__device__ unsigned g_h3[2][128];
__device__ unsigned long long g_cand[2][CAND_CAP];
__device__ unsigned g_eq[2][EQ_CAP];
__device__ unsigned g_candcnt[2];
__device__ unsigned g_eqcnt[2];
__device__ unsigned g_cntabove[2];
__device__ unsigned g_lokey[2], g_hikey[2];
__device__ unsigned g_B2[2], g_need2[2];
__device__ int g_vflag[2];   // 0 ok, 1 need<1 (take none), 2 need>cand (take all)

// ---------------------------------------------------------------------------
__global__ void asn_zero() {
    unsigned id = blockIdx.x * blockDim.x + threadIdx.x;
    unsigned stride = gridDim.x * blockDim.x;
    unsigned* s = &g_shist[0][0];
    for (unsigned i = id; i < 2 * NB_COARSE; i += stride) s[i] = 0u;
    unsigned* h1 = &g_h1[0][0];
    for (unsigned i = id; i < 2 * H1BINS; i += stride) h1[i] = 0u;
    unsigned* h3 = &g_h3[0][0];
    for (unsigned i = id; i < 256; i += stride) h3[i] = 0u;
    if (id < 2) {
        g_candcnt[id] = 0u;
        g_eqcnt[id] = 0u;
        g_cntabove[id] = 0u;
    }
}

// ---------------------------------------------------------------------------
// Sampled coarse histogram: SAMP_PM samples per matrix, taken as 32
// consecutive floats per line (1024 fully-used 128B lines spread evenly
// across the matrix). Few enough samples for direct global atomics.
__global__ void asn_sample(const float* in0, const float* in1) {
    int mat = blockIdx.y;
    const float* in = mat ? in1 : in0;
    int id = blockIdx.x * blockDim.x + threadIdx.x;
    int stride = gridDim.x * blockDim.x;
    for (int s = id; s < SAMP_PM; s += stride) {
        int idx = ((s >> 5) << 14) | (s & 31);   // line l at element 16384*l
        unsigned u = __float_as_uint(in[idx]) & 0x7fffffffu;
        atomicAdd(&g_shist[mat][u >> SHIFT], 1u);
    }
}

// ---------------------------------------------------------------------------
// Block-wide (1024-thread) inclusive suffix scan; buf has 2048 entries.
__device__ unsigned* suffix_scan_1024(unsigned v, unsigned* buf) {
    unsigned t = threadIdx.x;
    unsigned* a = buf;
    unsigned* b = buf + 1024;
    a[t] = v;
    __syncthreads();
    for (int d = 1; d < 1024; d <<= 1) {
        unsigned x = a[t] + ((t + d < 1024u) ? a[t + d] : 0u);
        b[t] = x;
        __syncthreads();
        unsigned* tmp = a; a = b; b = tmp;
    }
    return a;
}

// ---------------------------------------------------------------------------
// Pick 3-coarse-bin band around sampled threshold bin. grid=(2), 1024 thr.
__global__ void __launch_bounds__(1024) asn_range(unsigned m_samp) {
    int mat = blockIdx.x;
    __shared__ unsigned buf[2048];
    __shared__ int s_B;
    unsigned t = threadIdx.x;
    unsigned hb[8];
    unsigned v = 0;
#pragma unroll
    for (int j = 0; j < 8; j++) { hb[j] = g_shist[mat][t * 8 + j]; v += hb[j]; }
    unsigned* a = suffix_scan_1024(v, buf);
    unsigned need = m_samp;
    if (a[t] >= need && (t == 1023u || a[t + 1] < need)) {
        unsigned acc = (t == 1023u) ? 0u : a[t + 1];
        for (int j = 7; j >= 0; j--) {
            acc += hb[j];
            if (acc >= need) { s_B = (int)(t * 8 + (unsigned)j); break; }
        }
    }
    __syncthreads();
    if (t == 0) {
        int B = s_B;
        int lo = B - 1;
        if (lo < 0) lo = 0;
        int hi = lo + RANGE_COARSE;
        if (hi > NB_COARSE) { hi = NB_COARSE; lo = hi - RANGE_COARSE; }
        g_lokey[mat] = (unsigned)lo << SHIFT;
        g_hikey[mat] = (unsigned)hi << SHIFT;
    }
}

// ---------------------------------------------------------------------------
// Warp-private candidate push + flush (no block barriers).
__device__ __forceinline__ void asn_push(
    int mat, int w, unsigned lane,
    unsigned long long (*s_buf)[WBUF], unsigned* s_wcnt,
    unsigned long long pack)
{
    unsigned act = __activemask();
    unsigned lml = (1u << lane) - 1u;
    int leader = __ffs(act) - 1;
    unsigned cnt = __popc(act);
    unsigned rank = __popc(act & lml);
    unsigned p0 = s_wcnt[w];            // warp-private; all active lanes read same
    s_buf[w][p0 + rank] = pack;
    unsigned fcnt = p0 + cnt;
    if ((int)lane == leader) s_wcnt[w] = fcnt;
    if (fcnt >= WFLUSH) {
        __syncwarp(act);                 // make s_buf writes visible warp-wide
        unsigned base;
        if ((int)lane == leader) base = atomicAdd(&g_candcnt[mat], fcnt);
        base = __shfl_sync(act, base, leader);
        for (unsigned j = rank; j < fcnt; j += cnt) {
            unsigned slot = base + j;
            if (slot < CAND_CAP) g_cand[mat][slot] = s_buf[w][j];
        }
        if ((int)lane == leader) s_wcnt[w] = 0u;
    }
}

// ---------------------------------------------------------------------------
// Per-float4 processing for the mark pass.
__device__ __forceinline__ void asn_proc4(
    float4 v, unsigned base_idx, unsigned lo, unsigned hi, unsigned bw,
    int mat, int w, unsigned lane,
    unsigned long long (*s_buf)[WBUF], unsigned* s_wcnt,
    unsigned& myAbove, float4& ov)
{
    float vv[4] = {v.x, v.y, v.z, v.w};
    float o[4];
#pragma unroll
    for (int c = 0; c < 4; c++) {
        unsigned u = __float_as_uint(vv[c]) & 0x7fffffffu;
        unsigned rel = u - lo;
        bool above = (u >= hi);
        o[c] = above ? 1.0f : 0.0f;
        myAbove += above ? 1u : 0u;
        if (rel < bw) {   // candidate band [lo, hi)
            atomicAdd(&g_h1[mat][rel >> 7], 1u);   // 24KB, L2-resident
            asn_push(mat, w, lane, s_buf, s_wcnt,
                     ((unsigned long long)(base_idx + (unsigned)c) << 32) | rel);
        }
    }
    ov = make_float4(o[0], o[1], o[2], o[3]);
}

// ---------------------------------------------------------------------------
// Main pass: read input, write definite 1s/0s, compact band candidates,
// level-1 histogram (L2-resident), exact count of elements >= hi_key.
// MLP=2: two independent float4 loads issued back-to-back per iteration.
__global__ void __launch_bounds__(512) asn_mark(const float4* in0, const float4* in1,
                                                float* out, int n4, int n) {
    int mat = blockIdx.y;
    const float4* in = mat ? in1 : in0;
    float4* out4 = reinterpret_cast<float4*>(out) + (size_t)mat * n4;
    unsigned lo = g_lokey[mat], hi = g_hikey[mat];
    unsigned bw = hi - lo;

    __shared__ unsigned long long s_buf[NWARP][WBUF];
    __shared__ unsigned s_wcnt[NWARP];
    int w = threadIdx.x >> 5;
    unsigned lane = threadIdx.x & 31u;
    if (lane == 0) s_wcnt[w] = 0u;
    __syncwarp();

    unsigned myAbove = 0;
    unsigned gsize = gridDim.x * blockDim.x;
    unsigned gid = blockIdx.x * blockDim.x + threadIdx.x;

    for (unsigned i = gid; i < (unsigned)n4; i += 2u * gsize) {
        unsigned i2 = i + gsize;
        bool h2 = i2 < (unsigned)n4;
        float4 va = in[i];                       // both loads issue back-to-back
        float4 vb;
        if (h2) vb = in[i2];
        float4 oa, ob;
        asn_proc4(va, i * 4u, lo, hi, bw, mat, w, lane, s_buf, s_wcnt, myAbove, oa);
        out4[i] = oa;
        if (h2) {
            asn_proc4(vb, i2 * 4u, lo, hi, bw, mat, w, lane, s_buf, s_wcnt, myAbove, ob);
            out4[i2] = ob;
        }
    }

    // tail elements (n % 4), processed by block (0, mat)
    if (blockIdx.x == 0) {
        int start = n4 << 2;
        for (int i = start + (int)threadIdx.x; i < n; i += (int)blockDim.x) {
            const float* inf = (const float*)in;
            float* o = (float*)out4;
            unsigned u = __float_as_uint(inf[i]) & 0x7fffffffu;
            unsigned rel = u - lo;
            bool above = (u >= hi);
            o[i] = above ? 1.0f : 0.0f;
            myAbove += above ? 1u : 0u;
            if (rel < bw) {
                atomicAdd(&g_h1[mat][rel >> 7], 1u);
                asn_push(mat, w, lane, s_buf, s_wcnt,
                         ((unsigned long long)(unsigned)i << 32) | rel);
            }
        }
    }

    // final per-warp flush (full warp active here)
    {
        __syncwarp();
        unsigned fcnt = s_wcnt[w];
        if (fcnt) {
            unsigned base;
            if (lane == 0) base = atomicAdd(&g_candcnt[mat], fcnt);
            base = __shfl_sync(0xffffffffu, base, 0);
            for (unsigned j = lane; j < fcnt; j += 32u) {
                unsigned slot = base + j;
                if (slot < CAND_CAP) g_cand[mat][slot] = s_buf[w][j];
            }
        }
    }

    // block-level reduce of exact above-count (single global atomic per block)
    __shared__ unsigned s_red[NWARP];
    unsigned wsum = myAbove;
#pragma unroll
    for (int d = 16; d; d >>= 1) wsum += __shfl_down_sync(0xffffffffu, wsum, d);
    if (lane == 0) s_red[w] = wsum;
    __syncthreads();
    if (threadIdx.x == 0) {
        unsigned tot = 0;
        for (int k = 0; k < NWARP; k++) tot += s_red[k];
        atomicAdd(&g_cntabove[mat], tot);
    }
}

// ---------------------------------------------------------------------------
// Level-2: every block redundantly scans h1 (6144 L2-cached words) to find the
// winning level-1 bin B2 + need2, then filters candidates into h3[128].
__global__ void __launch_bounds__(1024) asn_sel2(unsigned m) {
    int mat = blockIdx.y;
    unsigned t = threadIdx.x;
    __shared__ unsigned buf[2048];
    __shared__ unsigned sh_B2, sh_need2;
    __shared__ int sh_vf;

    unsigned cAbove = g_cntabove[mat];
    unsigned cand = g_candcnt[mat];
    long long need_ll = (long long)m - (long long)cAbove;
    int vf = 0;
    if (need_ll < 1) vf = 1;
    else if (need_ll > (long long)cand || cand > CAND_CAP) vf = 2;
    if (t == 0) sh_vf = vf;

    if (vf == 0) {
        unsigned need = (unsigned)need_ll;
        unsigned hb[6];
        unsigned v = 0;
#pragma unroll
        for (int j = 0; j < 6; j++) { hb[j] = g_h1[mat][t * 6 + j]; v += hb[j]; }
        unsigned* a = suffix_scan_1024(v, buf);
        if (a[t] >= need && (t == 1023u || a[t + 1] < need)) {
            unsigned acc = (t == 1023u) ? 0u : a[t + 1];
            for (int j = 5; j >= 0; j--) {
                acc += hb[j];
                if (acc >= need) {
                    sh_B2 = t * 6u + (unsigned)j;
                    sh_need2 = need - (acc - hb[j]);
                    break;
                }
            }
        }
    }
    __syncthreads();
    if (sh_vf != 0) {
        if (blockIdx.x == 0 && t == 0) g_vflag[mat] = sh_vf;
        return;
    }
    if (blockIdx.x == 0 && t == 0) {
        g_vflag[mat] = 0;
        g_B2[mat] = sh_B2;
        g_need2[mat] = sh_need2;
    }
    unsigned B2 = sh_B2;
    if (cand > CAND_CAP) cand = CAND_CAP;
    unsigned id = blockIdx.x * blockDim.x + t;
    unsigned stride = gridDim.x * blockDim.x;
    for (unsigned i = id; i < cand; i += stride) {
        unsigned rel = (unsigned)(g_cand[mat][i] & 0xffffffffu);
        if ((rel >> 7) == B2) atomicAdd(&g_h3[mat][rel & 127u], 1u);
    }
}

// ---------------------------------------------------------------------------
// Redundant per-block final-threshold computation from h3[128].
// Returns F (rel threshold) and needK (ties to keep). Needs >=128 threads.
__device__ void asn_final(int mat, int* sF, unsigned* sNeedK) {
    __shared__ unsigned sh3[128];
    int vf = g_vflag[mat];
    if (vf == 1) { if (threadIdx.x == 0) { *sF = 0x7fffffff; *sNeedK = 0u; } __syncthreads(); return; }
    if (vf == 2) { if (threadIdx.x == 0) { *sF = -1; *sNeedK = 0u; } __syncthreads(); return; }
    if (threadIdx.x < 128) sh3[threadIdx.x] = g_h3[mat][threadIdx.x];
    __syncthreads();
    if (threadIdx.x == 0) {
        unsigned B2 = g_B2[mat], need2 = g_need2[mat];
        unsigned acc = 0;
        int F = 0x7fffffff; unsigned nk = 0u;
        for (int b = 127; b >= 0; b--) {
            acc += sh3[b];
            if (acc >= need2) {
                F = (int)(B2 * 128u + (unsigned)b);
                nk = need2 - (acc - sh3[b]);
                break;
            }
        }
        *sF = F; *sNeedK = nk;
    }
    __syncthreads();
}

// ---------------------------------------------------------------------------
// Candidate resolution: rel > F -> 1; rel == F -> tie buffer.
__global__ void __launch_bounds__(256) asn_cand(float* out, int n) {
    int mat = blockIdx.y;
    float* o = out + (size_t)mat * n;
    __shared__ int sF;
    __shared__ unsigned sNeedK;
    asn_final(mat, &sF, &sNeedK);
    int F = sF;
    unsigned cnt = g_candcnt[mat];
    if (cnt > CAND_CAP) cnt = CAND_CAP;
    unsigned id = blockIdx.x * blockDim.x + threadIdx.x;
    unsigned stride = gridDim.x * blockDim.x;
    unsigned lane = threadIdx.x & 31u;
    for (unsigned i = id; i < cnt; i += stride) {
        unsigned long long e = g_cand[mat][i];
        int rel = (int)(unsigned)(e & 0xffffffffu);
        unsigned idx = (unsigned)(e >> 32);
        if (rel > F) {
            o[idx] = 1.0f;
        } else if (rel == F) {
            unsigned act = __activemask();
            int leader = __ffs(act) - 1;
            unsigned p0;
            if ((int)lane == leader) p0 = atomicAdd(&g_eqcnt[mat], __popc(act));
            p0 = __shfl_sync(act, p0, leader);
            unsigned p = p0 + __popc(act & ((1u << lane) - 1u));
            if (p < EQ_CAP) g_eq[mat][p] = idx;
        }
    }
}

// ---------------------------------------------------------------------------
// Tie resolution: keep needK LARGEST indices among exact-threshold elements
// (stable ascending argsort keeps the tail => largest original indices).
__global__ void __launch_bounds__(256) asn_tie(float* out, int n) {
    int mat = blockIdx.x;
    float* o = out + (size_t)mat * n;
    __shared__ int sF;
    __shared__ unsigned sNeedK;
    asn_final(mat, &sF, &sNeedK);
    unsigned needK = sNeedK;
    unsigned cnt = g_eqcnt[mat];
    if (cnt > EQ_CAP) cnt = EQ_CAP;
    if (cnt == 0u || needK == 0u) return;
    if (needK >= cnt) {
        for (unsigned i = threadIdx.x; i < cnt; i += blockDim.x) o[g_eq[mat][i]] = 1.0f;
        return;
    }
    __shared__ unsigned s_red[8];
    __shared__ unsigned s_lo, s_hi;
    if (threadIdx.x == 0) { s_lo = 0u; s_hi = (unsigned)n; }
    __syncthreads();
    while (true) {
        unsigned lo = s_lo, hi = s_hi;
        if (lo + 1u >= hi) break;
        unsigned mid = lo + (hi - lo) / 2u;
        unsigned c = 0;
        for (unsigned i = threadIdx.x; i < cnt; i += blockDim.x)
            c += (g_eq[mat][i] >= mid) ? 1u : 0u;
#pragma unroll
        for (int d = 16; d; d >>= 1) c += __shfl_down_sync(0xffffffffu, c, d);
        if ((threadIdx.x & 31u) == 0) s_red[threadIdx.x >> 5] = c;
        __syncthreads();
        if (threadIdx.x == 0) {
            unsigned tot = 0;
            for (int k = 0; k < 8; k++) tot += s_red[k];
            if (tot >= needK) s_lo = mid; else s_hi = mid;
        }
        __syncthreads();
    }
    unsigned cut = s_lo;
    for (unsigned i = threadIdx.x; i < cnt; i += blockDim.x) {
        unsigned idx = g_eq[mat][i];
        if (idx >= cut) o[idx] = 1.0f;
    }
}

// ===========================================================================
extern "C" void kernel_launch(void* const* d_in, const int* in_sizes, int n_in,
                              void* d_out, int out_size) {
    const float* in0 = (const float*)d_in[0];
    const float* in1 = (const float*)d_in[1];
    float* out = (float*)d_out;
    int n = in_sizes[0];
    int n4 = n >> 2;

    // m = n - int(0.9 * n), matching python int() truncation semantics
    int j = (int)((1.0 - 0.1) * (double)n);
    unsigned m = (unsigned)(n - j);
    unsigned m_samp = (unsigned)((double)m * (double)SAMP_PM / (double)n);

    asn_zero<<<64, 256>>>();
    asn_sample<<<dim3(32, 2), 256>>>(in0, in1);
    asn_range<<<2, 1024>>>(m_samp);
    asn_mark<<<dim3(592, 2), 512>>>((const float4*)in0, (const float4*)in1, out, n4, n);
    asn_sel2<<<dim3(32, 2), 1024>>>(m);
    asn_cand<<<dim3(256, 2), 256>>>(out, n);
    asn_tie<<<2, 256>>>(out, n);
}

// round 16
// speedup vs baseline: 1.1159x; 1.1159x over previous
#include <cuda_runtime.h>

// ============================================================================
// AdapterSubnet top-k binary mask via sampled-bracket exact radix selection.
//
// key(x) = float_as_uint(|x|)  (31-bit, monotone with |x|)
// coarse bin = key >> 18  (8192 bins); band = 3 coarse bins around sampled
// threshold bin; rel = key - lo_key  (< 3*2^18).
// Selection inside the band: level-1 histogram h1[rel>>7] (6144 bins,
// L2-resident, filled by asn_mark), level-2 histogram h3[rel&127] over the
// winning level-1 bin (filled by asn_sel2 from the compacted candidates).
// Tie rule (stable argsort ascending, keep tail): among elements with
// key == threshold, keep the ones with LARGEST original indices.
//
// 5 launches: front2 (zero+sample+range fused, smem hist) -> mark (MLP=4)
//             -> sel2 -> cand -> tie
// ============================================================================

#define SHIFT 18
#define NB_COARSE (1 << (31 - SHIFT))   // 8192
#define RANGE_COARSE 3
#define RB (RANGE_COARSE << SHIFT)      // 786,432 rel values
#define H1BINS (RB >> 7)                // 6144
#define CAND_CAP (1u << 20)             // 1,048,576 candidates per matrix
#define EQ_CAP 65536
#define NWARP 16                        // 512 threads in asn_mark
#define WBUF 96                         // per-warp staging entries
#define WFLUSH 64                       // flush threshold
#define SAMP_PM 32768                   // samples per matrix (1024 x 128B lines)
#define ONEF 0x3f800000u                // bit pattern of 1.0f

__device__ unsigned g_h1[2][H1BINS];
__device__ unsigned g_h3[2][128];
__device__ unsigned long long g_cand[2][CAND_CAP];
__device__ unsigned g_eq[2][EQ_CAP];
__device__ unsigned g_candcnt[2];
__device__ unsigned g_eqcnt[2];
__device__ unsigned g_cntabove[2];
__device__ unsigned g_lokey[2], g_hikey[2];
__device__ unsigned g_B2[2], g_need2[2];
__device__ int g_vflag[2];   // 0 ok, 1 need<1 (take none), 2 need>cand (take all)

// ---------------------------------------------------------------------------
// Block-wide (1024-thread) inclusive suffix scan; buf has 2048 entries.
__device__ unsigned* suffix_scan_1024(unsigned v, unsigned* buf) {
    unsigned t = threadIdx.x;
    unsigned* a = buf;
    unsigned* b = buf + 1024;
    a[t] = v;
    __syncthreads();
    for (int d = 1; d < 1024; d <<= 1) {
        unsigned x = a[t] + ((t + d < 1024u) ? a[t + d] : 0u);
        b[t] = x;
        __syncthreads();
        unsigned* tmp = a; a = b; b = tmp;
    }
    return a;
}

// ---------------------------------------------------------------------------
// FRONT (fused): zero per-run global state + sampled coarse histogram in SMEM
// + band selection. grid = (2), 1024 threads; block b handles matrix b.
__global__ void __launch_bounds__(1024) asn_front2(const float* in0, const float* in1,
                                                   unsigned m_samp) {
    int mat = blockIdx.x;
    const float* in = mat ? in1 : in0;
    unsigned t = threadIdx.x;
    __shared__ unsigned sh[NB_COARSE];   // 32KB coarse histogram
    __shared__ unsigned buf[2048];       // scan scratch

    // ---- zero this matrix's global state (h1, h3, counters) ----
    for (unsigned i = t; i < H1BINS; i += 1024u) g_h1[mat][i] = 0u;
    if (t < 128) g_h3[mat][t] = 0u;
    if (t == 0) {
        g_candcnt[mat] = 0u;
        g_eqcnt[mat] = 0u;
        g_cntabove[mat] = 0u;
    }

    // ---- sampled coarse histogram in shared memory ----
    for (unsigned i = t; i < NB_COARSE; i += 1024u) sh[i] = 0u;
    __syncthreads();
    for (unsigned s = t; s < SAMP_PM; s += 1024u) {
        // 32 consecutive floats per fully-used 128B line; lines spread evenly
        unsigned idx = ((s >> 5) << 14) | (s & 31u);   // line l at element 16384*l
        unsigned u = __float_as_uint(in[idx]) & 0x7fffffffu;
        atomicAdd(&sh[u >> SHIFT], 1u);
    }
    __syncthreads();

    // ---- suffix scan of 8192 bins (8 per thread) -> pick threshold bin ----
    __shared__ int s_B;
    unsigned hb[8];
    unsigned v = 0;
#pragma unroll
    for (int j = 0; j < 8; j++) { hb[j] = sh[t * 8 + j]; v += hb[j]; }
    unsigned* a = suffix_scan_1024(v, buf);
    unsigned need = m_samp;
    if (a[t] >= need && (t == 1023u || a[t + 1] < need)) {
        unsigned acc = (t == 1023u) ? 0u : a[t + 1];
        for (int j = 7; j >= 0; j--) {
            acc += hb[j];
            if (acc >= need) { s_B = (int)(t * 8 + (unsigned)j); break; }
        }
    }
    __syncthreads();
    if (t == 0) {
        int B = s_B;
        int lo = B - 1;
        if (lo < 0) lo = 0;
        int hi = lo + RANGE_COARSE;
        if (hi > NB_COARSE) { hi = NB_COARSE; lo = hi - RANGE_COARSE; }
        g_lokey[mat] = (unsigned)lo << SHIFT;
        g_hikey[mat] = (unsigned)hi << SHIFT;
    }
}

// ---------------------------------------------------------------------------
// Warp-private candidate push + flush (no block barriers).
__device__ __forceinline__ void asn_push(
    int mat, int w, unsigned lane,
    unsigned long long (*s_buf)[WBUF], unsigned* s_wcnt,
    unsigned long long pack)
{
    unsigned act = __activemask();
    unsigned lml = (1u << lane) - 1u;
    int leader = __ffs(act) - 1;
    unsigned cnt = __popc(act);
    unsigned rank = __popc(act & lml);
    unsigned p0 = s_wcnt[w];            // warp-private; all active lanes read same
    s_buf[w][p0 + rank] = pack;
    unsigned fcnt = p0 + cnt;
    if ((int)lane == leader) s_wcnt[w] = fcnt;
    if (fcnt >= WFLUSH) {
        __syncwarp(act);                 // make s_buf writes visible warp-wide
        unsigned base;
        if ((int)lane == leader) base = atomicAdd(&g_candcnt[mat], fcnt);
        base = __shfl_sync(act, base, leader);
        for (unsigned j = rank; j < fcnt; j += cnt) {
            unsigned slot = base + j;
            if (slot < CAND_CAP) g_cand[mat][slot] = s_buf[w][j];
        }
        if ((int)lane == leader) s_wcnt[w] = 0u;
    }
}

// ---------------------------------------------------------------------------
// Per-uint4 processing for the mark pass (pure bit ops; 1.0f written as bits).
__device__ __forceinline__ void asn_proc4(
    uint4 v, unsigned base_idx, unsigned lo, unsigned hi, unsigned bw,
    int mat, int w, unsigned lane,
    unsigned long long (*s_buf)[WBUF], unsigned* s_wcnt,
    unsigned& myAbove, uint4& ov)
{
    unsigned uu[4] = {v.x, v.y, v.z, v.w};
    unsigned o[4];
#pragma unroll
    for (int c = 0; c < 4; c++) {
        unsigned u = uu[c] & 0x7fffffffu;
        unsigned rel = u - lo;
        bool above = (u >= hi);
        o[c] = above ? ONEF : 0u;
        myAbove += above ? 1u : 0u;
        if (rel < bw) {   // candidate band [lo, hi)
            atomicAdd(&g_h1[mat][rel >> 7], 1u);   // 24KB, L2-resident
            asn_push(mat, w, lane, s_buf, s_wcnt,
                     ((unsigned long long)(base_idx + (unsigned)c) << 32) | rel);
        }
    }
    ov = make_uint4(o[0], o[1], o[2], o[3]);
}

// ---------------------------------------------------------------------------
// Main pass: read input, write definite 1s/0s, compact band candidates,
// level-1 histogram (L2-resident), exact count of elements >= hi_key.
// MLP=4: four independent uint4 loads issued back-to-back per iteration
// (32 warps/SM x 4 x 128B x 148 SMs ~= 2.4MB in flight ~= BW*latency).
__global__ void __launch_bounds__(512) asn_mark(const uint4* in0, const uint4* in1,
                                                unsigned* out, int n4, int n) {
    int mat = blockIdx.y;
    const uint4* in = mat ? in1 : in0;
    uint4* out4 = reinterpret_cast<uint4*>(out) + (size_t)mat * n4;
    unsigned lo = g_lokey[mat], hi = g_hikey[mat];
    unsigned bw = hi - lo;

    __shared__ unsigned long long s_buf[NWARP][WBUF];
    __shared__ unsigned s_wcnt[NWARP];
    int w = threadIdx.x >> 5;
    unsigned lane = threadIdx.x & 31u;
    if (lane == 0) s_wcnt[w] = 0u;
    __syncwarp();

    unsigned myAbove = 0;
    unsigned gsize = gridDim.x * blockDim.x;
    unsigned gid = blockIdx.x * blockDim.x + threadIdx.x;

    for (unsigned i0 = gid; i0 < (unsigned)n4; i0 += 4u * gsize) {
        unsigned i1 = i0 + gsize, i2 = i0 + 2u * gsize, i3 = i0 + 3u * gsize;
        bool b1 = i1 < (unsigned)n4, b2 = i2 < (unsigned)n4, b3 = i3 < (unsigned)n4;
        uint4 v0 = in[i0];                  // all four loads issue back-to-back
        uint4 v1, v2, v3;
        if (b1) v1 = in[i1];
        if (b2) v2 = in[i2];
        if (b3) v3 = in[i3];
        uint4 o0, o1, o2, o3;
        asn_proc4(v0, i0 * 4u, lo, hi, bw, mat, w, lane, s_buf, s_wcnt, myAbove, o0);
        out4[i0] = o0;
        if (b1) {
            asn_proc4(v1, i1 * 4u, lo, hi, bw, mat, w, lane, s_buf, s_wcnt, myAbove, o1);
            out4[i1] = o1;
        }
        if (b2) {
            asn_proc4(v2, i2 * 4u, lo, hi, bw, mat, w, lane, s_buf, s_wcnt, myAbove, o2);
            out4[i2] = o2;
        }
        if (b3) {
            asn_proc4(v3, i3 * 4u, lo, hi, bw, mat, w, lane, s_buf, s_wcnt, myAbove, o3);
            out4[i3] = o3;
        }
    }

    // tail elements (n % 4), processed by block (0, mat)
    if (blockIdx.x == 0) {
        int start = n4 << 2;
        for (int i = start + (int)threadIdx.x; i < n; i += (int)blockDim.x) {
            const unsigned* inf = (const unsigned*)in;
            unsigned* o = (unsigned*)out4;
            unsigned u = inf[i] & 0x7fffffffu;
            unsigned rel = u - lo;
            bool above = (u >= hi);
            o[i] = above ? ONEF : 0u;
            myAbove += above ? 1u : 0u;
            if (rel < bw) {
                atomicAdd(&g_h1[mat][rel >> 7], 1u);
                asn_push(mat, w, lane, s_buf, s_wcnt,
                         ((unsigned long long)(unsigned)i << 32) | rel);
            }
        }
    }

    // final per-warp flush (full warp active here)
    {
        __syncwarp();
        unsigned fcnt = s_wcnt[w];
        if (fcnt) {
            unsigned base;
            if (lane == 0) base = atomicAdd(&g_candcnt[mat], fcnt);
            base = __shfl_sync(0xffffffffu, base, 0);
            for (unsigned j = lane; j < fcnt; j += 32u) {
                unsigned slot = base + j;
                if (slot < CAND_CAP) g_cand[mat][slot] = s_buf[w][j];
            }
        }
    }

    // block-level reduce of exact above-count (single global atomic per block)
    __shared__ unsigned s_red[NWARP];
    unsigned wsum = myAbove;
#pragma unroll
    for (int d = 16; d; d >>= 1) wsum += __shfl_down_sync(0xffffffffu, wsum, d);
    if (lane == 0) s_red[w] = wsum;
    __syncthreads();
    if (threadIdx.x == 0) {
        unsigned tot = 0;
        for (int k = 0; k < NWARP; k++) tot += s_red[k];
        atomicAdd(&g_cntabove[mat], tot);
    }
}

// ---------------------------------------------------------------------------
// Level-2: every block redundantly scans h1 (6144 L2-cached words) to find the
// winning level-1 bin B2 + need2, then filters candidates into h3[128].
__global__ void __launch_bounds__(1024) asn_sel2(unsigned m) {
    int mat = blockIdx.y;
    unsigned t = threadIdx.x;
    __shared__ unsigned buf[2048];
    __shared__ unsigned sh_B2, sh_need2;
    __shared__ int sh_vf;

    unsigned cAbove = g_cntabove[mat];
    unsigned cand = g_candcnt[mat];
    long long need_ll = (long long)m - (long long)cAbove;
    int vf = 0;
    if (need_ll < 1) vf = 1;
    else if (need_ll > (long long)cand || cand > CAND_CAP) vf = 2;
    if (t == 0) sh_vf = vf;

    if (vf == 0) {
        unsigned need = (unsigned)need_ll;
        unsigned hb[6];
        unsigned v = 0;
#pragma unroll
        for (int j = 0; j < 6; j++) { hb[j] = g_h1[mat][t * 6 + j]; v += hb[j]; }
        unsigned* a = suffix_scan_1024(v, buf);
        if (a[t] >= need && (t == 1023u || a[t + 1] < need)) {
            unsigned acc = (t == 1023u) ? 0u : a[t + 1];
            for (int j = 5; j >= 0; j--) {
                acc += hb[j];
                if (acc >= need) {
                    sh_B2 = t * 6u + (unsigned)j;
                    sh_need2 = need - (acc - hb[j]);
                    break;
                }
            }
        }
    }
    __syncthreads();
    if (sh_vf != 0) {
        if (blockIdx.x == 0 && t == 0) g_vflag[mat] = sh_vf;
        return;
    }
    if (blockIdx.x == 0 && t == 0) {
        g_vflag[mat] = 0;
        g_B2[mat] = sh_B2;
        g_need2[mat] = sh_need2;
    }
    unsigned B2 = sh_B2;
    if (cand > CAND_CAP) cand = CAND_CAP;
    unsigned id = blockIdx.x * blockDim.x + t;
    unsigned stride = gridDim.x * blockDim.x;
    for (unsigned i = id; i < cand; i += stride) {
        unsigned rel = (unsigned)(g_cand[mat][i] & 0xffffffffu);
        if ((rel >> 7) == B2) atomicAdd(&g_h3[mat][rel & 127u], 1u);
    }
}

// ---------------------------------------------------------------------------
// Redundant per-block final-threshold computation from h3[128].
// Returns F (rel threshold) and needK (ties to keep). Needs >=128 threads.
__device__ void asn_final(int mat, int* sF, unsigned* sNeedK) {
    __shared__ unsigned sh3[128];
    int vf = g_vflag[mat];
    if (vf == 1) { if (threadIdx.x == 0) { *sF = 0x7fffffff; *sNeedK = 0u; } __syncthreads(); return; }
    if (vf == 2) { if (threadIdx.x == 0) { *sF = -1; *sNeedK = 0u; } __syncthreads(); return; }
    if (threadIdx.x < 128) sh3[threadIdx.x] = g_h3[mat][threadIdx.x];
    __syncthreads();
    if (threadIdx.x == 0) {
        unsigned B2 = g_B2[mat], need2 = g_need2[mat];
        unsigned acc = 0;
        int F = 0x7fffffff; unsigned nk = 0u;
        for (int b = 127; b >= 0; b--) {
            acc += sh3[b];
            if (acc >= need2) {
                F = (int)(B2 * 128u + (unsigned)b);
                nk = need2 - (acc - sh3[b]);
                break;
            }
        }
        *sF = F; *sNeedK = nk;
    }
    __syncthreads();
}

// ---------------------------------------------------------------------------
// Candidate resolution: rel > F -> 1; rel == F -> tie buffer.
__global__ void __launch_bounds__(256) asn_cand(float* out, int n) {
    int mat = blockIdx.y;
    float* o = out + (size_t)mat * n;
    __shared__ int sF;
    __shared__ unsigned sNeedK;
    asn_final(mat, &sF, &sNeedK);
    int F = sF;
    unsigned cnt = g_candcnt[mat];
    if (cnt > CAND_CAP) cnt = CAND_CAP;
    unsigned id = blockIdx.x * blockDim.x + threadIdx.x;
    unsigned stride = gridDim.x * blockDim.x;
    unsigned lane = threadIdx.x & 31u;
    for (unsigned i = id; i < cnt; i += stride) {
        unsigned long long e = g_cand[mat][i];
        int rel = (int)(unsigned)(e & 0xffffffffu);
        unsigned idx = (unsigned)(e >> 32);
        if (rel > F) {
            o[idx] = 1.0f;
        } else if (rel == F) {
            unsigned act = __activemask();
            int leader = __ffs(act) - 1;
            unsigned p0;
            if ((int)lane == leader) p0 = atomicAdd(&g_eqcnt[mat], __popc(act));
            p0 = __shfl_sync(act, p0, leader);
            unsigned p = p0 + __popc(act & ((1u << lane) - 1u));
            if (p < EQ_CAP) g_eq[mat][p] = idx;
        }
    }
}

// ---------------------------------------------------------------------------
// Tie resolution: keep needK LARGEST indices among exact-threshold elements
// (stable ascending argsort keeps the tail => largest original indices).
__global__ void __launch_bounds__(256) asn_tie(float* out, int n) {
    int mat = blockIdx.x;
    float* o = out + (size_t)mat * n;
    __shared__ int sF;
    __shared__ unsigned sNeedK;
    asn_final(mat, &sF, &sNeedK);
    unsigned needK = sNeedK;
    unsigned cnt = g_eqcnt[mat];
    if (cnt > EQ_CAP) cnt = EQ_CAP;
    if (cnt == 0u || needK == 0u) return;
    if (needK >= cnt) {
        for (unsigned i = threadIdx.x; i < cnt; i += blockDim.x) o[g_eq[mat][i]] = 1.0f;
        return;
    }
    __shared__ unsigned s_red[8];
    __shared__ unsigned s_lo, s_hi;
    if (threadIdx.x == 0) { s_lo = 0u; s_hi = (unsigned)n; }
    __syncthreads();
    while (true) {
        unsigned lo = s_lo, hi = s_hi;
        if (lo + 1u >= hi) break;
        unsigned mid = lo + (hi - lo) / 2u;
        unsigned c = 0;
        for (unsigned i = threadIdx.x; i < cnt; i += blockDim.x)
            c += (g_eq[mat][i] >= mid) ? 1u : 0u;
#pragma unroll
        for (int d = 16; d; d >>= 1) c += __shfl_down_sync(0xffffffffu, c, d);
        if ((threadIdx.x & 31u) == 0) s_red[threadIdx.x >> 5] = c;
        __syncthreads();
        if (threadIdx.x == 0) {
            unsigned tot = 0;
            for (int k = 0; k < 8; k++) tot += s_red[k];
            if (tot >= needK) s_lo = mid; else s_hi = mid;
        }
        __syncthreads();
    }
    unsigned cut = s_lo;
    for (unsigned i = threadIdx.x; i < cnt; i += blockDim.x) {
        unsigned idx = g_eq[mat][i];
        if (idx >= cut) o[idx] = 1.0f;
    }
}

// ===========================================================================
extern "C" void kernel_launch(void* const* d_in, const int* in_sizes, int n_in,
                              void* d_out, int out_size) {
    const float* in0 = (const float*)d_in[0];
    const float* in1 = (const float*)d_in[1];
    float* out = (float*)d_out;
    int n = in_sizes[0];
    int n4 = n >> 2;

    // m = n - int(0.9 * n), matching python int() truncation semantics
    int j = (int)((1.0 - 0.1) * (double)n);
    unsigned m = (unsigned)(n - j);
    unsigned m_samp = (unsigned)((double)m * (double)SAMP_PM / (double)n);

    asn_front2<<<2, 1024>>>(in0, in1, m_samp);
    asn_mark<<<dim3(592, 2), 512>>>((const uint4*)in0, (const uint4*)in1,
                                    (unsigned*)out, n4, n);
    asn_sel2<<<dim3(32, 2), 1024>>>(m);
    asn_cand<<<dim3(256, 2), 256>>>(out, n);
    asn_tie<<<2, 256>>>(out, n);
}